// round 14
// baseline (speedup 1.0000x reference)
#include <cuda_runtime.h>
#include <cstdint>

#define NN 50000
#define EE 800000
#define BDIM 64          // NBASES*FH
#define CWDIM 32         // NHEADS*NBASES

// ------------- scratch (device globals; referenced ONLY in device code) -----
__device__ float g_dis[NN];
__device__ int   g_row[EE];
__device__ int   g_col[EE];
__device__ int   g_cnt[NN];
__device__ int   g_off[NN + 1];
__device__ int   g_cur[NN];
__device__ int   g_csr[EE];          // row ids grouped by col
__device__ __align__(16) float g_sb [NN * BDIM];   // dis-scaled bases
__device__ float g_cw [NN * CWDIM];  // combination weights per node
__device__ float g_h1 [NN * 128];
__device__ float g_h2 [NN * 128];
__device__ float g_pre0[NN * 2];
__device__ float g_pre1[NN * 2];
__device__ int   g_is64;

// ------------- dtype detection (int64 vs int32 edge_index) -----------------
__global__ void k_detect(const unsigned int* __restrict__ ei_words) {
    __shared__ int nz;
    int t = threadIdx.x;  // 128 threads
    if (t == 0) nz = 0;
    __syncthreads();
    unsigned int w = ei_words[2 * (t * 997 + 1) + 1];
    if (w != 0) atomicOr(&nz, 1);
    __syncthreads();
    if (t == 0) g_is64 = (nz == 0);
}

__global__ void k_zero_cnt() {
    int v = blockIdx.x * blockDim.x + threadIdx.x;
    if (v < NN) g_cnt[v] = 0;
}

// decode edges + in-degree histogram
__global__ void k_prep_edges(const void* __restrict__ ei) {
    int e = blockIdx.x * blockDim.x + threadIdx.x;
    if (e >= EE) return;
    int r, c;
    if (g_is64) {
        const long long* p = (const long long*)ei;
        r = (int)p[e];
        c = (int)p[EE + e];
    } else {
        const int* p = (const int*)ei;
        r = p[e];
        c = p[EE + e];
    }
    g_row[e] = r;
    g_col[e] = c;
    atomicAdd(&g_cnt[c], 1);
}

// single-block scan over 50K counts; also computes dis = rsqrt(1+deg)
__global__ void k_scan() {
    __shared__ int part[1024];
    int t = threadIdx.x;                    // 1024 threads
    const int CH = (NN + 1023) / 1024;      // 49
    int lo = t * CH;
    int hi = lo + CH; if (hi > NN) hi = NN;
    int s = 0;
    for (int i = lo; i < hi; i++) s += g_cnt[i];
    part[t] = s;
    __syncthreads();
    // Hillis-Steele inclusive scan
    for (int d = 1; d < 1024; d <<= 1) {
        int v = (t >= d) ? part[t - d] : 0;
        __syncthreads();
        part[t] += v;
        __syncthreads();
    }
    int run = (t > 0) ? part[t - 1] : 0;
    for (int i = lo; i < hi; i++) {
        g_off[i] = run;
        g_cur[i] = run;
        int c = g_cnt[i];
        run += c;
        g_dis[i] = rsqrtf(1.0f + (float)c);
    }
    if (t == 1023) g_off[NN] = run;
}

// fill CSR: for each edge, append its row id to col's bucket
__global__ void k_fill() {
    int e = blockIdx.x * blockDim.x + threadIdx.x;
    if (e >= EE) return;
    int pos = atomicAdd(&g_cur[g_col[e]], 1);
    g_csr[pos] = g_row[e];
}

// ------------- fused GEMM: [N,128] x [128, 64+32] ---------------------------
// layer==0: X = Xin (param). layer==1: X = g_h1 (device-side reference)
// writes g_sb (cols 0..63, scaled by dis) and g_cw (cols 64..95, + bc)
__global__ void k_gemm(const float* __restrict__ Xin, int layer,
                       const float* __restrict__ Wb,
                       const float* __restrict__ Wc,
                       const float* __restrict__ bc) {
    const float* X = (layer == 0) ? Xin : g_h1;
    __shared__ float Xs[32][33];   // 32 rows x 32 K
    __shared__ float Ws[32][96];   // 32 K x 96 cols
    int row0 = blockIdx.x * 32;
    int tx = threadIdx.x;          // 256
    int r  = tx >> 3;              // 0..31 (row within tile)
    int cg = tx & 7;               // 0..7  (12 cols each)

    float acc[12];
#pragma unroll
    for (int j = 0; j < 12; j++) acc[j] = 0.f;

    for (int kb = 0; kb < 4; kb++) {
        for (int i = tx; i < 32 * 32; i += 256) {
            int rr = i >> 5, kk = i & 31;
            int grow = row0 + rr;
            Xs[rr][kk] = (grow < NN) ? X[grow * 128 + kb * 32 + kk] : 0.f;
        }
        for (int i = tx; i < 32 * 96; i += 256) {
            int kk = i / 96, cc = i % 96;
            int k = kb * 32 + kk;
            Ws[kk][cc] = (cc < 64) ? Wb[k * 64 + cc] : Wc[k * 32 + (cc - 64)];
        }
        __syncthreads();
#pragma unroll
        for (int k = 0; k < 32; k++) {
            float xv = Xs[r][k];
#pragma unroll
            for (int j = 0; j < 12; j++)
                acc[j] += xv * Ws[k][cg * 12 + j];
        }
        __syncthreads();
    }

    int grow = row0 + r;
    if (grow < NN) {
        float dv = g_dis[grow];
#pragma unroll
        for (int j = 0; j < 12; j++) {
            int c = cg * 12 + j;
            if (c < 64) g_sb[grow * 64 + c] = dv * acc[j];
            else        g_cw[grow * 32 + (c - 64)] = acc[j] + bc[c - 64];
        }
    }
}

// ------------- fused gather + combine ---------------------------------------
// warp per node: agg[lane], agg[lane+32] accumulated in registers over
// in-edges (self-loop as init), then dis[v]-scaled, einsum'd with cw, + bias.
__global__ void k_aggcomb(const float* __restrict__ bias, int layer) {
    __shared__ float sAgg[8][64];
    __shared__ float sCw[8][32];
    int warp = threadIdx.x >> 5;
    int lane = threadIdx.x & 31;
    int v = blockIdx.x * 8 + warp;      // 6250 * 8 == 50000 exactly

    int s  = g_off[v];
    int e2 = g_off[v + 1];
    float acc0 = g_sb[v * 64 + lane];        // self-loop term
    float acc1 = g_sb[v * 64 + 32 + lane];

    int j = s;
    for (; j + 1 < e2; j += 2) {             // unroll 2 -> MLP 4
        int r0 = g_csr[j];
        int r1 = g_csr[j + 1];
        float a0 = g_sb[r0 * 64 + lane];
        float b0 = g_sb[r0 * 64 + 32 + lane];
        float a1 = g_sb[r1 * 64 + lane];
        float b1 = g_sb[r1 * 64 + 32 + lane];
        acc0 += a0 + a1;
        acc1 += b0 + b1;
    }
    if (j < e2) {
        int r0 = g_csr[j];
        acc0 += g_sb[r0 * 64 + lane];
        acc1 += g_sb[r0 * 64 + 32 + lane];
    }

    float dv = g_dis[v];
    sAgg[warp][lane]      = dv * acc0;
    sAgg[warp][lane + 32] = dv * acc1;
    sCw[warp][lane] = g_cw[v * 32 + lane];
    __syncwarp();

#pragma unroll
    for (int t = 0; t < 4; t++) {
        int o  = lane + 32 * t;              // output index 0..127
        int hh = o >> 4, f = o & 15;
        float sum = bias[o];
#pragma unroll
        for (int b = 0; b < 4; b++)
            sum += sCw[warp][hh * 4 + b] * sAgg[warp][b * 16 + f];
        if (layer == 0) g_h1[v * 128 + o] = fmaxf(sum, 0.f);
        else            g_h2[v * 128 + o] = sum;
    }
}

// ------------- classifier precompute: pre0 = h2@Wcls[:128], pre1 = h2@Wcls[128:]
__global__ void k_precls(const float* __restrict__ Wcls) {
    int gt = blockIdx.x * blockDim.x + threadIdx.x;
    int v = gt >> 5;
    int lane = gt & 31;
    if (v >= NN) return;
    float a00 = 0.f, a01 = 0.f, a10 = 0.f, a11 = 0.f;
#pragma unroll
    for (int i = 0; i < 4; i++) {
        int k = lane + i * 32;
        float hv = g_h2[v * 128 + k];
        a00 += hv * Wcls[k * 2 + 0];
        a01 += hv * Wcls[k * 2 + 1];
        a10 += hv * Wcls[(128 + k) * 2 + 0];
        a11 += hv * Wcls[(128 + k) * 2 + 1];
    }
#pragma unroll
    for (int o = 16; o; o >>= 1) {
        a00 += __shfl_xor_sync(0xffffffffu, a00, o);
        a01 += __shfl_xor_sync(0xffffffffu, a01, o);
        a10 += __shfl_xor_sync(0xffffffffu, a10, o);
        a11 += __shfl_xor_sync(0xffffffffu, a11, o);
    }
    if (lane == 0) {
        g_pre0[v * 2 + 0] = a00;
        g_pre0[v * 2 + 1] = a01;
        g_pre1[v * 2 + 0] = a10;
        g_pre1[v * 2 + 1] = a11;
    }
}

// ------------- edge output: out[e][o] = pre0[src][o] + pre1[dst][o] + bcls[o]
__global__ void k_edgeout(const float* __restrict__ bcls,
                          float* __restrict__ out) {
    int t = blockIdx.x * blockDim.x + threadIdx.x;
    if (t >= EE * 2) return;
    int e = t >> 1;
    int o = t & 1;
    out[t] = g_pre0[g_row[e] * 2 + o] + g_pre1[g_col[e] * 2 + o] + bcls[o];
}

// ------------- launch: resolve inputs BY SIZE (order-agnostic) --------------
extern "C" void kernel_launch(void* const* d_in, const int* in_sizes, int n_in,
                              void* d_out, int out_size) {
    const float *x = 0, *Wb1 = 0, *Wc1 = 0, *bc1 = 0, *b1 = 0;
    const float *Wb2 = 0, *Wc2 = 0, *bc2 = 0, *b2 = 0, *Wcls = 0, *bcls = 0;
    const void* ei = 0;

    for (int i = 0; i < n_in; i++) {
        const float* p = (const float*)d_in[i];
        switch (in_sizes[i]) {
            case 6400000: x = p; break;                       // [50000,128]
            case 1600000: ei = d_in[i]; break;                // [2,800000]
            case 8192:    if (!Wb1) Wb1 = p; else Wb2 = p; break;
            case 4096:    if (!Wc1) Wc1 = p; else Wc2 = p; break;
            case 512:     Wcls = p; break;
            case 128:     if (!b1) b1 = p; else b2 = p; break;
            case 32:      if (!bc1) bc1 = p; else bc2 = p; break;
            case 2:       bcls = p; break;
            default: break;
        }
    }
    if (!x && n_in >= 12) {   // positional fallback (canonical dict order)
        x = (const float*)d_in[0]; ei = d_in[1];
        Wb1 = (const float*)d_in[2]; Wc1 = (const float*)d_in[3];
        bc1 = (const float*)d_in[4]; b1 = (const float*)d_in[5];
        Wb2 = (const float*)d_in[6]; Wc2 = (const float*)d_in[7];
        bc2 = (const float*)d_in[8]; b2 = (const float*)d_in[9];
        Wcls = (const float*)d_in[10]; bcls = (const float*)d_in[11];
    }
    float* out = (float*)d_out;

    // ---- graph prep: CSR by col ----
    k_detect<<<1, 128>>>((const unsigned int*)ei);
    k_zero_cnt<<<(NN + 255) / 256, 256>>>();
    k_prep_edges<<<(EE + 255) / 256, 256>>>(ei);
    k_scan<<<1, 1024>>>();
    k_fill<<<(EE + 255) / 256, 256>>>();

    // ---- layer 1 ----
    k_gemm<<<(NN + 31) / 32, 256>>>(x, 0, Wb1, Wc1, bc1);
    k_aggcomb<<<NN / 8, 256>>>(b1, 0);

    // ---- layer 2 ----
    k_gemm<<<(NN + 31) / 32, 256>>>(x, 1, Wb2, Wc2, bc2);
    k_aggcomb<<<NN / 8, 256>>>(b2, 1);

    // ---- edge classifier ----
    k_precls<<<(NN * 32 + 255) / 256, 256>>>(Wcls);
    k_edgeout<<<(EE * 2 + 255) / 256, 256>>>(bcls, out);
}

// round 15
// speedup vs baseline: 1.3182x; 1.3182x over previous
#include <cuda_runtime.h>
#include <cstdint>

#define NN 50000
#define EE 800000
#define BDIM 64          // NBASES*FH
#define CWDIM 32         // NHEADS*NBASES
#define NBLK 196         // ceil(NN/256)

// ------------- scratch (device globals; referenced ONLY in device code) -----
__device__ float g_dis[NN];
__device__ int   g_row[EE];
__device__ int   g_col[EE];
__device__ int   g_cnt[NN];
__device__ int   g_off[NN + 1];
__device__ int   g_cur[NN];
__device__ int   g_csr[EE];          // row ids grouped by col
__device__ int   g_bsum[NBLK];
__device__ int   g_boff[NBLK];
__device__ __align__(16) float g_sb [NN * BDIM];   // dis-scaled bases
__device__ float g_cw [NN * CWDIM];  // combination weights per node
__device__ float g_h1 [NN * 128];
__device__ float g_h2 [NN * 128];
__device__ float g_pre0[NN * 2];
__device__ float g_pre1[NN * 2];
__device__ int   g_is64;

// ------------- dtype detection (int64 vs int32 edge_index) -----------------
__global__ void k_detect(const unsigned int* __restrict__ ei_words) {
    __shared__ int nz;
    int t = threadIdx.x;  // 128 threads
    if (t == 0) nz = 0;
    __syncthreads();
    unsigned int w = ei_words[2 * (t * 997 + 1) + 1];
    if (w != 0) atomicOr(&nz, 1);
    __syncthreads();
    if (t == 0) g_is64 = (nz == 0);
}

__global__ void k_zero_cnt() {
    int v = blockIdx.x * blockDim.x + threadIdx.x;
    if (v < NN) g_cnt[v] = 0;
}

// decode edges + in-degree histogram
__global__ void k_prep_edges(const void* __restrict__ ei) {
    int e = blockIdx.x * blockDim.x + threadIdx.x;
    if (e >= EE) return;
    int r, c;
    if (g_is64) {
        const long long* p = (const long long*)ei;
        r = (int)p[e];
        c = (int)p[EE + e];
    } else {
        const int* p = (const int*)ei;
        r = p[e];
        c = p[EE + e];
    }
    g_row[e] = r;
    g_col[e] = c;
    atomicAdd(&g_cnt[c], 1);
}

// ---- stage 1: per-block reduction of 256 counts ----
__global__ void k_bsum() {
    __shared__ int s[256];
    int t = threadIdx.x;
    int i = blockIdx.x * 256 + t;
    s[t] = (i < NN) ? g_cnt[i] : 0;
    __syncthreads();
    for (int d = 128; d; d >>= 1) {
        if (t < d) s[t] += s[t + d];
        __syncthreads();
    }
    if (t == 0) g_bsum[blockIdx.x] = s[0];
}

// ---- stage 2: one small block scans the 196 block sums (exclusive) ----
__global__ void k_bscan() {
    __shared__ int s[256];
    int t = threadIdx.x;
    int v = (t < NBLK) ? g_bsum[t] : 0;
    s[t] = v;
    __syncthreads();
    for (int d = 1; d < 256; d <<= 1) {
        int u = (t >= d) ? s[t - d] : 0;
        __syncthreads();
        s[t] += u;
        __syncthreads();
    }
    if (t < NBLK) g_boff[t] = s[t] - v;   // exclusive
    if (t == 0) g_off[NN] = EE;
}

// ---- stage 3: per-block exclusive scan + base; write off/cur/dis ----
__global__ void k_final() {
    __shared__ int s[256];
    int t = threadIdx.x;
    int i = blockIdx.x * 256 + t;
    int c = (i < NN) ? g_cnt[i] : 0;
    s[t] = c;
    __syncthreads();
    for (int d = 1; d < 256; d <<= 1) {
        int u = (t >= d) ? s[t - d] : 0;
        __syncthreads();
        s[t] += u;
        __syncthreads();
    }
    if (i < NN) {
        int base = g_boff[blockIdx.x] + s[t] - c;  // exclusive prefix
        g_off[i] = base;
        g_cur[i] = base;
        g_dis[i] = rsqrtf(1.0f + (float)c);
    }
}

// fill CSR: for each edge, append its row id to col's bucket
__global__ void k_fill() {
    int e = blockIdx.x * blockDim.x + threadIdx.x;
    if (e >= EE) return;
    int pos = atomicAdd(&g_cur[g_col[e]], 1);
    g_csr[pos] = g_row[e];
}

// ------------- fused GEMM: [N,128] x [128, 64+32] ---------------------------
// layer==0: X = Xin (param). layer==1: X = g_h1 (device-side reference)
// writes g_sb (cols 0..63, scaled by dis) and g_cw (cols 64..95, + bc)
__global__ void k_gemm(const float* __restrict__ Xin, int layer,
                       const float* __restrict__ Wb,
                       const float* __restrict__ Wc,
                       const float* __restrict__ bc) {
    const float* X = (layer == 0) ? Xin : g_h1;
    __shared__ float Xs[32][33];   // 32 rows x 32 K
    __shared__ float Ws[32][96];   // 32 K x 96 cols
    int row0 = blockIdx.x * 32;
    int tx = threadIdx.x;          // 256
    int r  = tx >> 3;              // 0..31 (row within tile)
    int cg = tx & 7;               // 0..7  (12 cols each)

    float acc[12];
#pragma unroll
    for (int j = 0; j < 12; j++) acc[j] = 0.f;

    for (int kb = 0; kb < 4; kb++) {
        for (int i = tx; i < 32 * 32; i += 256) {
            int rr = i >> 5, kk = i & 31;
            int grow = row0 + rr;
            Xs[rr][kk] = (grow < NN) ? X[grow * 128 + kb * 32 + kk] : 0.f;
        }
        for (int i = tx; i < 32 * 96; i += 256) {
            int kk = i / 96, cc = i % 96;
            int k = kb * 32 + kk;
            Ws[kk][cc] = (cc < 64) ? Wb[k * 64 + cc] : Wc[k * 32 + (cc - 64)];
        }
        __syncthreads();
#pragma unroll
        for (int k = 0; k < 32; k++) {
            float xv = Xs[r][k];
#pragma unroll
            for (int j = 0; j < 12; j++)
                acc[j] += xv * Ws[k][cg * 12 + j];
        }
        __syncthreads();
    }

    int grow = row0 + r;
    if (grow < NN) {
        float dv = g_dis[grow];
#pragma unroll
        for (int j = 0; j < 12; j++) {
            int c = cg * 12 + j;
            if (c < 64) g_sb[grow * 64 + c] = dv * acc[j];
            else        g_cw[grow * 32 + (c - 64)] = acc[j] + bc[c - 64];
        }
    }
}

// ------------- fused gather + combine ---------------------------------------
// warp per node: agg[lane], agg[lane+32] accumulated in registers over
// in-edges (self-loop as init), then dis[v]-scaled, einsum'd with cw, + bias.
__global__ void k_aggcomb(const float* __restrict__ bias, int layer) {
    __shared__ float sAgg[8][64];
    __shared__ float sCw[8][32];
    int warp = threadIdx.x >> 5;
    int lane = threadIdx.x & 31;
    int v = blockIdx.x * 8 + warp;      // 6250 * 8 == 50000 exactly

    int s  = g_off[v];
    int e2 = g_off[v + 1];
    float acc0 = g_sb[v * 64 + lane];        // self-loop term
    float acc1 = g_sb[v * 64 + 32 + lane];

    int j = s;
    for (; j + 1 < e2; j += 2) {             // unroll 2 -> MLP 4
        int r0 = g_csr[j];
        int r1 = g_csr[j + 1];
        float a0 = g_sb[r0 * 64 + lane];
        float b0 = g_sb[r0 * 64 + 32 + lane];
        float a1 = g_sb[r1 * 64 + lane];
        float b1 = g_sb[r1 * 64 + 32 + lane];
        acc0 += a0 + a1;
        acc1 += b0 + b1;
    }
    if (j < e2) {
        int r0 = g_csr[j];
        acc0 += g_sb[r0 * 64 + lane];
        acc1 += g_sb[r0 * 64 + 32 + lane];
    }

    float dv = g_dis[v];
    sAgg[warp][lane]      = dv * acc0;
    sAgg[warp][lane + 32] = dv * acc1;
    sCw[warp][lane] = g_cw[v * 32 + lane];
    __syncwarp();

#pragma unroll
    for (int t = 0; t < 4; t++) {
        int o  = lane + 32 * t;              // output index 0..127
        int hh = o >> 4, f = o & 15;
        float sum = bias[o];
#pragma unroll
        for (int b = 0; b < 4; b++)
            sum += sCw[warp][hh * 4 + b] * sAgg[warp][b * 16 + f];
        if (layer == 0) g_h1[v * 128 + o] = fmaxf(sum, 0.f);
        else            g_h2[v * 128 + o] = sum;
    }
}

// ------------- classifier precompute: pre0 = h2@Wcls[:128], pre1 = h2@Wcls[128:]
__global__ void k_precls(const float* __restrict__ Wcls) {
    int gt = blockIdx.x * blockDim.x + threadIdx.x;
    int v = gt >> 5;
    int lane = gt & 31;
    if (v >= NN) return;
    float a00 = 0.f, a01 = 0.f, a10 = 0.f, a11 = 0.f;
#pragma unroll
    for (int i = 0; i < 4; i++) {
        int k = lane + i * 32;
        float hv = g_h2[v * 128 + k];
        a00 += hv * Wcls[k * 2 + 0];
        a01 += hv * Wcls[k * 2 + 1];
        a10 += hv * Wcls[(128 + k) * 2 + 0];
        a11 += hv * Wcls[(128 + k) * 2 + 1];
    }
#pragma unroll
    for (int o = 16; o; o >>= 1) {
        a00 += __shfl_xor_sync(0xffffffffu, a00, o);
        a01 += __shfl_xor_sync(0xffffffffu, a01, o);
        a10 += __shfl_xor_sync(0xffffffffu, a10, o);
        a11 += __shfl_xor_sync(0xffffffffu, a11, o);
    }
    if (lane == 0) {
        g_pre0[v * 2 + 0] = a00;
        g_pre0[v * 2 + 1] = a01;
        g_pre1[v * 2 + 0] = a10;
        g_pre1[v * 2 + 1] = a11;
    }
}

// ------------- edge output: out[e][o] = pre0[src][o] + pre1[dst][o] + bcls[o]
__global__ void k_edgeout(const float* __restrict__ bcls,
                          float* __restrict__ out) {
    int t = blockIdx.x * blockDim.x + threadIdx.x;
    if (t >= EE * 2) return;
    int e = t >> 1;
    int o = t & 1;
    out[t] = g_pre0[g_row[e] * 2 + o] + g_pre1[g_col[e] * 2 + o] + bcls[o];
}

// ------------- launch: resolve inputs BY SIZE (order-agnostic) --------------
extern "C" void kernel_launch(void* const* d_in, const int* in_sizes, int n_in,
                              void* d_out, int out_size) {
    const float *x = 0, *Wb1 = 0, *Wc1 = 0, *bc1 = 0, *b1 = 0;
    const float *Wb2 = 0, *Wc2 = 0, *bc2 = 0, *b2 = 0, *Wcls = 0, *bcls = 0;
    const void* ei = 0;

    for (int i = 0; i < n_in; i++) {
        const float* p = (const float*)d_in[i];
        switch (in_sizes[i]) {
            case 6400000: x = p; break;                       // [50000,128]
            case 1600000: ei = d_in[i]; break;                // [2,800000]
            case 8192:    if (!Wb1) Wb1 = p; else Wb2 = p; break;
            case 4096:    if (!Wc1) Wc1 = p; else Wc2 = p; break;
            case 512:     Wcls = p; break;
            case 128:     if (!b1) b1 = p; else b2 = p; break;
            case 32:      if (!bc1) bc1 = p; else bc2 = p; break;
            case 2:       bcls = p; break;
            default: break;
        }
    }
    if (!x && n_in >= 12) {   // positional fallback (canonical dict order)
        x = (const float*)d_in[0]; ei = d_in[1];
        Wb1 = (const float*)d_in[2]; Wc1 = (const float*)d_in[3];
        bc1 = (const float*)d_in[4]; b1 = (const float*)d_in[5];
        Wb2 = (const float*)d_in[6]; Wc2 = (const float*)d_in[7];
        bc2 = (const float*)d_in[8]; b2 = (const float*)d_in[9];
        Wcls = (const float*)d_in[10]; bcls = (const float*)d_in[11];
    }
    float* out = (float*)d_out;

    // ---- graph prep: CSR by col (two-level parallel scan) ----
    k_detect<<<1, 128>>>((const unsigned int*)ei);
    k_zero_cnt<<<NBLK, 256>>>();
    k_prep_edges<<<(EE + 255) / 256, 256>>>(ei);
    k_bsum<<<NBLK, 256>>>();
    k_bscan<<<1, 256>>>();
    k_final<<<NBLK, 256>>>();
    k_fill<<<(EE + 255) / 256, 256>>>();

    // ---- layer 1 ----
    k_gemm<<<(NN + 31) / 32, 256>>>(x, 0, Wb1, Wc1, bc1);
    k_aggcomb<<<NN / 8, 256>>>(b1, 0);

    // ---- layer 2 ----
    k_gemm<<<(NN + 31) / 32, 256>>>(x, 1, Wb2, Wc2, bc2);
    k_aggcomb<<<NN / 8, 256>>>(b2, 1);

    // ---- edge classifier ----
    k_precls<<<(NN * 32 + 255) / 256, 256>>>(Wcls);
    k_edgeout<<<(EE * 2 + 255) / 256, 256>>>(bcls, out);
}

// round 16
// speedup vs baseline: 2.0989x; 1.5923x over previous
#include <cuda_runtime.h>
#include <cstdint>

#define NN 50000
#define EE 800000
#define BDIM 64          // NBASES*FH
#define CWDIM 32         // NHEADS*NBASES
#define NBLK 196         // ceil(NN/256)

// ------------- scratch (device globals; referenced ONLY in device code) -----
__device__ float g_dis[NN];
__device__ int   g_row[EE];
__device__ int   g_col[EE];
__device__ int   g_cnt[NN];
__device__ int   g_off[NN + 1];
__device__ int   g_cur[NN];
__device__ int   g_csr[EE];          // row ids grouped by col
__device__ int   g_bsum[NBLK];
__device__ int   g_boff[NBLK];
__device__ __align__(16) float g_sb [NN * BDIM];   // dis-scaled bases
__device__ float g_cw [NN * CWDIM];  // combination weights per node
__device__ __align__(16) float g_h1 [NN * 128];
__device__ float2 g_pre0[NN];
__device__ float2 g_pre1[NN];
__device__ int   g_is64;

// ------------- dtype detection (int64 vs int32 edge_index) -----------------
__global__ void k_detect(const unsigned int* __restrict__ ei_words) {
    __shared__ int nz;
    int t = threadIdx.x;  // 128 threads
    if (t == 0) nz = 0;
    __syncthreads();
    unsigned int w = ei_words[2 * (t * 997 + 1) + 1];
    if (w != 0) atomicOr(&nz, 1);
    __syncthreads();
    if (t == 0) g_is64 = (nz == 0);
}

__global__ void k_zero_cnt() {
    int v = blockIdx.x * blockDim.x + threadIdx.x;
    if (v < NN) g_cnt[v] = 0;
}

// decode edges + in-degree histogram
__global__ void k_prep_edges(const void* __restrict__ ei) {
    int e = blockIdx.x * blockDim.x + threadIdx.x;
    if (e >= EE) return;
    int r, c;
    if (g_is64) {
        const long long* p = (const long long*)ei;
        r = (int)p[e];
        c = (int)p[EE + e];
    } else {
        const int* p = (const int*)ei;
        r = p[e];
        c = p[EE + e];
    }
    g_row[e] = r;
    g_col[e] = c;
    atomicAdd(&g_cnt[c], 1);
}

// ---- stage 1: per-block reduction of 256 counts ----
__global__ void k_bsum() {
    __shared__ int s[256];
    int t = threadIdx.x;
    int i = blockIdx.x * 256 + t;
    s[t] = (i < NN) ? g_cnt[i] : 0;
    __syncthreads();
    for (int d = 128; d; d >>= 1) {
        if (t < d) s[t] += s[t + d];
        __syncthreads();
    }
    if (t == 0) g_bsum[blockIdx.x] = s[0];
}

// ---- stage 2: one small block scans the 196 block sums (exclusive) ----
__global__ void k_bscan() {
    __shared__ int s[256];
    int t = threadIdx.x;
    int v = (t < NBLK) ? g_bsum[t] : 0;
    s[t] = v;
    __syncthreads();
    for (int d = 1; d < 256; d <<= 1) {
        int u = (t >= d) ? s[t - d] : 0;
        __syncthreads();
        s[t] += u;
        __syncthreads();
    }
    if (t < NBLK) g_boff[t] = s[t] - v;   // exclusive
    if (t == 0) g_off[NN] = EE;
}

// ---- stage 3: per-block exclusive scan + base; write off/cur/dis ----
__global__ void k_final() {
    __shared__ int s[256];
    int t = threadIdx.x;
    int i = blockIdx.x * 256 + t;
    int c = (i < NN) ? g_cnt[i] : 0;
    s[t] = c;
    __syncthreads();
    for (int d = 1; d < 256; d <<= 1) {
        int u = (t >= d) ? s[t - d] : 0;
        __syncthreads();
        s[t] += u;
        __syncthreads();
    }
    if (i < NN) {
        int base = g_boff[blockIdx.x] + s[t] - c;  // exclusive prefix
        g_off[i] = base;
        g_cur[i] = base;
        g_dis[i] = rsqrtf(1.0f + (float)c);
    }
}

// fill CSR: for each edge, append its row id to col's bucket
__global__ void k_fill() {
    int e = blockIdx.x * blockDim.x + threadIdx.x;
    if (e >= EE) return;
    int pos = atomicAdd(&g_cur[g_col[e]], 1);
    g_csr[pos] = g_row[e];
}

// ------------- fused GEMM: [N,128] x [128, 64+32] ---------------------------
// 64-row x 96-col block tile, 4x6 register tile per thread (256 threads).
// layer==0: X = Xin (param). layer==1: X = g_h1 (device-side reference)
// writes g_sb (cols 0..63, scaled by dis) and g_cw (cols 64..95, + bc)
__global__ void __launch_bounds__(256) k_gemm(
        const float* __restrict__ Xin, int layer,
        const float* __restrict__ Wb,
        const float* __restrict__ Wc,
        const float* __restrict__ bc) {
    const float* X = (layer == 0) ? Xin : g_h1;
    __shared__ float Xs[64][33];
    __shared__ float Ws[32][96];
    int tid = threadIdx.x;
    int tx = tid & 15;         // col group: cols tx*6 .. tx*6+5
    int ty = tid >> 4;         // row group: rows ty*4 .. ty*4+3
    int row0 = blockIdx.x * 64;

    float acc[4][6];
#pragma unroll
    for (int i = 0; i < 4; i++)
#pragma unroll
        for (int j = 0; j < 6; j++) acc[i][j] = 0.f;

    for (int kb = 0; kb < 4; kb++) {
        // load X tile: 64 rows x 32 K  (512 float4, 2 per thread)
#pragma unroll
        for (int i = tid; i < 512; i += 256) {
            int rr = i >> 3;           // 0..63
            int qq = i & 7;            // float4 within row
            int grow = row0 + rr;
            float4 v = make_float4(0.f, 0.f, 0.f, 0.f);
            if (grow < NN)
                v = *(const float4*)(X + grow * 128 + kb * 32 + qq * 4);
            Xs[rr][qq * 4 + 0] = v.x;
            Xs[rr][qq * 4 + 1] = v.y;
            Xs[rr][qq * 4 + 2] = v.z;
            Xs[rr][qq * 4 + 3] = v.w;
        }
        // load W tile: 32 K x 96 cols
#pragma unroll
        for (int i = tid; i < 3072; i += 256) {
            int kk = i / 96, cc = i % 96;
            int k = kb * 32 + kk;
            Ws[kk][cc] = (cc < 64) ? Wb[k * 64 + cc] : Wc[k * 32 + (cc - 64)];
        }
        __syncthreads();
#pragma unroll
        for (int k = 0; k < 32; k++) {
            float xv[4], wv[6];
#pragma unroll
            for (int i = 0; i < 4; i++) xv[i] = Xs[ty * 4 + i][k];
#pragma unroll
            for (int j = 0; j < 6; j++) wv[j] = Ws[k][tx * 6 + j];
#pragma unroll
            for (int i = 0; i < 4; i++)
#pragma unroll
                for (int j = 0; j < 6; j++)
                    acc[i][j] += xv[i] * wv[j];
        }
        __syncthreads();
    }

#pragma unroll
    for (int i = 0; i < 4; i++) {
        int grow = row0 + ty * 4 + i;
        if (grow < NN) {
            float dv = g_dis[grow];
#pragma unroll
            for (int j = 0; j < 6; j++) {
                int c = tx * 6 + j;
                if (c < 64) g_sb[grow * 64 + c] = dv * acc[i][j];
                else        g_cw[grow * 32 + (c - 64)] = acc[i][j] + bc[c - 64];
            }
        }
    }
}

// ------------- fused gather + combine (+classifier on layer 2) --------------
// warp per node: agg[lane], agg[lane+32] accumulated in registers over
// in-edges (self-loop as init), then dis[v]-scaled, einsum'd with cw + bias.
// layer==0: write h1 (relu). layer==1: fold directly into pre0/pre1 via Wcls.
__global__ void k_aggcomb(const float* __restrict__ bias, int layer,
                          const float* __restrict__ Wcls) {
    __shared__ float sAgg[8][64];
    __shared__ float sCw[8][32];
    int warp = threadIdx.x >> 5;
    int lane = threadIdx.x & 31;
    int v = blockIdx.x * 8 + warp;      // 6250 * 8 == 50000 exactly

    int s  = g_off[v];
    int e2 = g_off[v + 1];
    float acc0 = g_sb[v * 64 + lane];        // self-loop term
    float acc1 = g_sb[v * 64 + 32 + lane];

    int j = s;
    for (; j + 1 < e2; j += 2) {             // unroll 2 -> MLP 4
        int r0 = g_csr[j];
        int r1 = g_csr[j + 1];
        float a0 = g_sb[r0 * 64 + lane];
        float b0 = g_sb[r0 * 64 + 32 + lane];
        float a1 = g_sb[r1 * 64 + lane];
        float b1 = g_sb[r1 * 64 + 32 + lane];
        acc0 += a0 + a1;
        acc1 += b0 + b1;
    }
    if (j < e2) {
        int r0 = g_csr[j];
        acc0 += g_sb[r0 * 64 + lane];
        acc1 += g_sb[r0 * 64 + 32 + lane];
    }

    float dv = g_dis[v];
    sAgg[warp][lane]      = dv * acc0;
    sAgg[warp][lane + 32] = dv * acc1;
    sCw[warp][lane] = g_cw[v * 32 + lane];
    __syncwarp();

    if (layer == 0) {
#pragma unroll
        for (int t = 0; t < 4; t++) {
            int o  = lane + 32 * t;              // output index 0..127
            int hh = o >> 4, f = o & 15;
            float sum = bias[o];
#pragma unroll
            for (int b = 0; b < 4; b++)
                sum += sCw[warp][hh * 4 + b] * sAgg[warp][b * 16 + f];
            g_h1[v * 128 + o] = fmaxf(sum, 0.f);
        }
    } else {
        float a00 = 0.f, a01 = 0.f, a10 = 0.f, a11 = 0.f;
#pragma unroll
        for (int t = 0; t < 4; t++) {
            int o  = lane + 32 * t;
            int hh = o >> 4, f = o & 15;
            float sum = bias[o];
#pragma unroll
            for (int b = 0; b < 4; b++)
                sum += sCw[warp][hh * 4 + b] * sAgg[warp][b * 16 + f];
            a00 += sum * Wcls[o * 2 + 0];
            a01 += sum * Wcls[o * 2 + 1];
            a10 += sum * Wcls[(128 + o) * 2 + 0];
            a11 += sum * Wcls[(128 + o) * 2 + 1];
        }
#pragma unroll
        for (int o = 16; o; o >>= 1) {
            a00 += __shfl_xor_sync(0xffffffffu, a00, o);
            a01 += __shfl_xor_sync(0xffffffffu, a01, o);
            a10 += __shfl_xor_sync(0xffffffffu, a10, o);
            a11 += __shfl_xor_sync(0xffffffffu, a11, o);
        }
        if (lane == 0) {
            g_pre0[v] = make_float2(a00, a01);
            g_pre1[v] = make_float2(a10, a11);
        }
    }
}

// ------------- edge output: out[e] = pre0[src] + pre1[dst] + bcls -----------
__global__ void k_edgeout(const float* __restrict__ bcls,
                          float2* __restrict__ out) {
    int e = blockIdx.x * blockDim.x + threadIdx.x;
    if (e >= EE) return;
    float2 p0 = g_pre0[g_row[e]];
    float2 p1 = g_pre1[g_col[e]];
    out[e] = make_float2(p0.x + p1.x + bcls[0], p0.y + p1.y + bcls[1]);
}

// ------------- launch: resolve inputs BY SIZE (order-agnostic) --------------
extern "C" void kernel_launch(void* const* d_in, const int* in_sizes, int n_in,
                              void* d_out, int out_size) {
    const float *x = 0, *Wb1 = 0, *Wc1 = 0, *bc1 = 0, *b1 = 0;
    const float *Wb2 = 0, *Wc2 = 0, *bc2 = 0, *b2 = 0, *Wcls = 0, *bcls = 0;
    const void* ei = 0;

    for (int i = 0; i < n_in; i++) {
        const float* p = (const float*)d_in[i];
        switch (in_sizes[i]) {
            case 6400000: x = p; break;                       // [50000,128]
            case 1600000: ei = d_in[i]; break;                // [2,800000]
            case 8192:    if (!Wb1) Wb1 = p; else Wb2 = p; break;
            case 4096:    if (!Wc1) Wc1 = p; else Wc2 = p; break;
            case 512:     Wcls = p; break;
            case 128:     if (!b1) b1 = p; else b2 = p; break;
            case 32:      if (!bc1) bc1 = p; else bc2 = p; break;
            case 2:       bcls = p; break;
            default: break;
        }
    }
    if (!x && n_in >= 12) {   // positional fallback (canonical dict order)
        x = (const float*)d_in[0]; ei = d_in[1];
        Wb1 = (const float*)d_in[2]; Wc1 = (const float*)d_in[3];
        bc1 = (const float*)d_in[4]; b1 = (const float*)d_in[5];
        Wb2 = (const float*)d_in[6]; Wc2 = (const float*)d_in[7];
        bc2 = (const float*)d_in[8]; b2 = (const float*)d_in[9];
        Wcls = (const float*)d_in[10]; bcls = (const float*)d_in[11];
    }
    float2* out = (float2*)d_out;

    // ---- graph prep: CSR by col (two-level parallel scan) ----
    k_detect<<<1, 128>>>((const unsigned int*)ei);
    k_zero_cnt<<<NBLK, 256>>>();
    k_prep_edges<<<(EE + 255) / 256, 256>>>(ei);
    k_bsum<<<NBLK, 256>>>();
    k_bscan<<<1, 256>>>();
    k_final<<<NBLK, 256>>>();
    k_fill<<<(EE + 255) / 256, 256>>>();

    // ---- layer 1 ----
    k_gemm<<<(NN + 63) / 64, 256>>>(x, 0, Wb1, Wc1, bc1);
    k_aggcomb<<<NN / 8, 256>>>(b1, 0, Wcls);

    // ---- layer 2 (classifier precompute fused in) ----
    k_gemm<<<(NN + 63) / 64, 256>>>(x, 1, Wb2, Wc2, bc2);
    k_aggcomb<<<NN / 8, 256>>>(b2, 1, Wcls);

    // ---- edge output ----
    k_edgeout<<<(EE + 255) / 256, 256>>>(bcls, out);
}